// round 1
// baseline (speedup 1.0000x reference)
#include <cuda_runtime.h>
#include <math.h>

#define D_EMBED 1024
#define N_HEAD  16
#define D_HEAD  64
#define B_SZ    4
#define SEQ     2048
#define M_TOT   (B_SZ * SEQ)          // 8192
#define SCALE_F 0.03125f               // 1024^-0.5

// ---------------- scratch (device globals; no cudaMalloc allowed) ----------
__device__ __align__(256) float g_q[B_SZ * N_HEAD * SEQ * D_HEAD];
__device__ __align__(256) float g_k[B_SZ * N_HEAD * SEQ * D_HEAD];
__device__ __align__(256) float g_v[B_SZ * N_HEAD * SEQ * D_HEAD];
__device__ __align__(256) float g_attn[M_TOT * D_EMBED];

// ---------------------------------------------------------------------------
// Tiled NT GEMM: C[M,N] = A[M,K] * B[N,K]^T + bias
// BM=BN=64, BK=16, 256 threads, 4x4 micro-tile per thread.
// MODE 1: A = x, scatter epilogue into g_q/g_k/g_v with [B,H,S,Dh] layout.
// MODE 0: A = g_attn (device global), plain epilogue into `out`.
// ---------------------------------------------------------------------------
template <int MODE>
__global__ void __launch_bounds__(256)
gemm_nt(const float* __restrict__ Aparam,
        const float* __restrict__ Bw,
        const float* __restrict__ bias,
        float* __restrict__ out,
        int N, int K)
{
    const float* A = (MODE == 0) ? (const float*)g_attn : Aparam;

    __shared__ __align__(16) float As[16 * 68];
    __shared__ __align__(16) float Bs[16 * 68];

    const int tid = threadIdx.x;
    const int m0 = blockIdx.y * 64;
    const int n0 = blockIdx.x * 64;
    const int ty = tid >> 4;        // 0..15
    const int tx = tid & 15;        // 0..15

    // loader mapping: each thread loads one float4 of A and one of B per k-step
    const int lrow = tid >> 2;            // 0..63
    const int lk   = (tid & 3) * 4;       // 0,4,8,12

    const float* Ap = A  + (size_t)(m0 + lrow) * K + lk;
    const float* Bp = Bw + (size_t)(n0 + lrow) * K + lk;

    float acc[4][4];
#pragma unroll
    for (int i = 0; i < 4; i++)
#pragma unroll
        for (int j = 0; j < 4; j++) acc[i][j] = 0.f;

    for (int kb = 0; kb < K; kb += 16) {
        const float4 av = *(const float4*)(Ap + kb);
        const float4 bv = *(const float4*)(Bp + kb);
        __syncthreads();   // previous compute done before overwriting smem
        As[(lk + 0) * 68 + lrow] = av.x;
        As[(lk + 1) * 68 + lrow] = av.y;
        As[(lk + 2) * 68 + lrow] = av.z;
        As[(lk + 3) * 68 + lrow] = av.w;
        Bs[(lk + 0) * 68 + lrow] = bv.x;
        Bs[(lk + 1) * 68 + lrow] = bv.y;
        Bs[(lk + 2) * 68 + lrow] = bv.z;
        Bs[(lk + 3) * 68 + lrow] = bv.w;
        __syncthreads();

#pragma unroll
        for (int k = 0; k < 16; k++) {
            const float4 a4 = *(const float4*)&As[k * 68 + ty * 4];
            const float4 b4 = *(const float4*)&Bs[k * 68 + tx * 4];
            const float a[4] = {a4.x, a4.y, a4.z, a4.w};
            const float b[4] = {b4.x, b4.y, b4.z, b4.w};
#pragma unroll
            for (int i = 0; i < 4; i++)
#pragma unroll
                for (int j = 0; j < 4; j++) acc[i][j] += a[i] * b[j];
        }
    }

    const int e0 = n0 + tx * 4;
    const float4 bias4 = *(const float4*)&bias[e0];

    if (MODE == 0) {
#pragma unroll
        for (int i = 0; i < 4; i++) {
            const int m = m0 + ty * 4 + i;
            float4 r;
            r.x = acc[i][0] + bias4.x;
            r.y = acc[i][1] + bias4.y;
            r.z = acc[i][2] + bias4.z;
            r.w = acc[i][3] + bias4.w;
            *(float4*)&out[(size_t)m * N + e0] = r;
        }
    } else {
        // e0..e0+3 share the same (q/k/v choice, head) since n0 is a multiple of 64
        const int c  = e0 / D_EMBED;            // 0=q,1=k,2=v
        const int hh = (e0 / D_HEAD) % N_HEAD;
        const int dh = e0 % D_HEAD;             // multiple of 4
        float* dst = (c == 0) ? g_q : (c == 1) ? g_k : g_v;
#pragma unroll
        for (int i = 0; i < 4; i++) {
            const int m = m0 + ty * 4 + i;
            const int b = m >> 11;              // /2048
            const int s = m & 2047;
            float4 r;
            r.x = acc[i][0] + bias4.x;
            r.y = acc[i][1] + bias4.y;
            r.z = acc[i][2] + bias4.z;
            r.w = acc[i][3] + bias4.w;
            *(float4*)&dst[((size_t)((b * N_HEAD + hh) * SEQ + s)) * D_HEAD + dh] = r;
        }
    }
}

// ---------------------------------------------------------------------------
// Flash-attention (causal), fp32. One block = one (b,h) x 64-query tile.
// Smem: Qs (transposed [d][q]), KPs (K transposed [d][k], reused for P^T [k][q]),
// Vs ([k][d]). Stride 68 floats (16B-aligned rows, low bank conflicts).
// ---------------------------------------------------------------------------
#define ATT_STRIDE 68
#define ATT_SMEM_BYTES (3 * 64 * ATT_STRIDE * 4)

__global__ void __launch_bounds__(256)
attn_kernel()
{
    extern __shared__ __align__(16) float sm[];
    float* Qs  = sm;                       // 64*68
    float* KPs = sm + 64 * ATT_STRIDE;     // K^T, then P^T
    float* Vs  = sm + 2 * 64 * ATT_STRIDE;

    const int qt = blockIdx.x;             // 0..31
    const int bh = blockIdx.y;             // 0..63
    const int tid = threadIdx.x;
    const int ty = tid >> 4, tx = tid & 15;

    const float* Qp = g_q + (size_t)bh * SEQ * D_HEAD;
    const float* Kp = g_k + (size_t)bh * SEQ * D_HEAD;
    const float* Vp = g_v + (size_t)bh * SEQ * D_HEAD;

    // load Q tile transposed: Qs[d][r]
    for (int idx = tid; idx < 64 * 16; idx += 256) {
        const int r  = idx >> 4;
        const int d4 = (idx & 15) * 4;
        const float4 v = *(const float4*)&Qp[(size_t)(qt * 64 + r) * D_HEAD + d4];
        Qs[(d4 + 0) * ATT_STRIDE + r] = v.x;
        Qs[(d4 + 1) * ATT_STRIDE + r] = v.y;
        Qs[(d4 + 2) * ATT_STRIDE + r] = v.z;
        Qs[(d4 + 3) * ATT_STRIDE + r] = v.w;
    }

    float o[4][4];
    float mrow[4], lrow[4];
#pragma unroll
    for (int i = 0; i < 4; i++) {
        mrow[i] = -INFINITY; lrow[i] = 0.f;
#pragma unroll
        for (int j = 0; j < 4; j++) o[i][j] = 0.f;
    }

    for (int kt = 0; kt <= qt; kt++) {
        __syncthreads();   // previous P/V reads done before overwrite
        for (int idx = tid; idx < 64 * 16; idx += 256) {
            const int r  = idx >> 4;
            const int d4 = (idx & 15) * 4;
            const float4 kv = *(const float4*)&Kp[(size_t)(kt * 64 + r) * D_HEAD + d4];
            KPs[(d4 + 0) * ATT_STRIDE + r] = kv.x;
            KPs[(d4 + 1) * ATT_STRIDE + r] = kv.y;
            KPs[(d4 + 2) * ATT_STRIDE + r] = kv.z;
            KPs[(d4 + 3) * ATT_STRIDE + r] = kv.w;
            const float4 vv = *(const float4*)&Vp[(size_t)(kt * 64 + r) * D_HEAD + d4];
            *(float4*)&Vs[r * ATT_STRIDE + d4] = vv;
        }
        __syncthreads();

        // S = Q K^T (4x4 per thread)
        float s[4][4];
#pragma unroll
        for (int i = 0; i < 4; i++)
#pragma unroll
            for (int j = 0; j < 4; j++) s[i][j] = 0.f;
#pragma unroll 8
        for (int d = 0; d < 64; d++) {
            const float4 a4 = *(const float4*)&Qs[d * ATT_STRIDE + ty * 4];
            const float4 b4 = *(const float4*)&KPs[d * ATT_STRIDE + tx * 4];
            const float a[4] = {a4.x, a4.y, a4.z, a4.w};
            const float b[4] = {b4.x, b4.y, b4.z, b4.w};
#pragma unroll
            for (int i = 0; i < 4; i++)
#pragma unroll
                for (int j = 0; j < 4; j++) s[i][j] += a[i] * b[j];
        }

        // scale + causal mask (only diagonal tile needs it)
        const int qg0 = qt * 64 + ty * 4;
        const int kg0 = kt * 64 + tx * 4;
#pragma unroll
        for (int i = 0; i < 4; i++)
#pragma unroll
            for (int j = 0; j < 4; j++) {
                s[i][j] *= SCALE_F;
                if (kt == qt && (kg0 + j) > (qg0 + i)) s[i][j] = -INFINITY;
            }

        // row max across the 16 tx threads (lanes 0-15 / 16-31 groups)
        float mt[4], mnew[4], alpha[4], rs[4];
#pragma unroll
        for (int i = 0; i < 4; i++) {
            mt[i] = fmaxf(fmaxf(s[i][0], s[i][1]), fmaxf(s[i][2], s[i][3]));
#pragma unroll
            for (int off = 8; off > 0; off >>= 1)
                mt[i] = fmaxf(mt[i], __shfl_xor_sync(0xffffffffu, mt[i], off));
            mnew[i]  = fmaxf(mrow[i], mt[i]);
            alpha[i] = expf(mrow[i] - mnew[i]);
        }
#pragma unroll
        for (int i = 0; i < 4; i++) {
            rs[i] = 0.f;
#pragma unroll
            for (int j = 0; j < 4; j++) {
                s[i][j] = expf(s[i][j] - mnew[i]);
                rs[i] += s[i][j];
            }
#pragma unroll
            for (int off = 8; off > 0; off >>= 1)
                rs[i] += __shfl_xor_sync(0xffffffffu, rs[i], off);
            lrow[i] = alpha[i] * lrow[i] + rs[i];
            mrow[i] = mnew[i];
#pragma unroll
            for (int j = 0; j < 4; j++) o[i][j] *= alpha[i];
        }

        __syncthreads();   // everyone done reading K^T from KPs
        // store P transposed: KPs[k][q]
#pragma unroll
        for (int j = 0; j < 4; j++) {
            float4 pv;
            pv.x = s[0][j]; pv.y = s[1][j]; pv.z = s[2][j]; pv.w = s[3][j];
            *(float4*)&KPs[(tx * 4 + j) * ATT_STRIDE + ty * 4] = pv;
        }
        __syncthreads();

        // O += P V
#pragma unroll 8
        for (int k = 0; k < 64; k++) {
            const float4 a4 = *(const float4*)&KPs[k * ATT_STRIDE + ty * 4];
            const float4 b4 = *(const float4*)&Vs[k * ATT_STRIDE + tx * 4];
            const float a[4] = {a4.x, a4.y, a4.z, a4.w};
            const float b[4] = {b4.x, b4.y, b4.z, b4.w};
#pragma unroll
            for (int i = 0; i < 4; i++)
#pragma unroll
                for (int j = 0; j < 4; j++) o[i][j] += a[i] * b[j];
        }
    }

    // epilogue: normalize + write back to [B,S,D] layout for the out-proj GEMM
    const int b = bh >> 4, h = bh & 15;
#pragma unroll
    for (int i = 0; i < 4; i++) {
        const float inv = 1.f / lrow[i];
        const int sg = qt * 64 + ty * 4 + i;
        float4 r;
        r.x = o[i][0] * inv; r.y = o[i][1] * inv;
        r.z = o[i][2] * inv; r.w = o[i][3] * inv;
        *(float4*)&g_attn[((size_t)(b * SEQ + sg)) * D_EMBED + h * D_HEAD + tx * 4] = r;
    }
}

// ---------------------------------------------------------------------------
extern "C" void kernel_launch(void* const* d_in, const int* in_sizes, int n_in,
                              void* d_out, int out_size)
{
    const float* x     = (const float*)d_in[0];   // [4,2048,1024]
    const float* w_in  = (const float*)d_in[1];   // [3072,1024]
    const float* b_in  = (const float*)d_in[2];   // [3072]
    const float* w_out = (const float*)d_in[3];   // [1024,1024]
    const float* b_out = (const float*)d_in[4];   // [1024]
    float* out = (float*)d_out;                   // [4,2048,1024]
    (void)in_sizes; (void)n_in; (void)out_size;

    cudaFuncSetAttribute(attn_kernel,
                         cudaFuncAttributeMaxDynamicSharedMemorySize,
                         ATT_SMEM_BYTES);

    // 1) QKV projection + bias, scattered into [B,H,S,Dh] scratch
    gemm_nt<1><<<dim3(3 * D_EMBED / 64, M_TOT / 64), 256>>>(
        x, w_in, b_in, nullptr, 3 * D_EMBED, D_EMBED);

    // 2) causal flash attention -> g_attn in [B,S,D]
    attn_kernel<<<dim3(SEQ / 64, B_SZ * N_HEAD), 256, ATT_SMEM_BYTES>>>();

    // 3) output projection + bias
    gemm_nt<0><<<dim3(D_EMBED / 64, M_TOT / 64), 256>>>(
        nullptr, w_out, b_out, out, D_EMBED, D_EMBED);
}

// round 3
// speedup vs baseline: 1.7527x; 1.7527x over previous
#include <cuda_runtime.h>
#include <math.h>
#include <stdint.h>

#define D_EMBED 1024
#define N_HEAD  16
#define D_HEAD  64
#define B_SZ    4
#define SEQ     2048
#define M_TOT   (B_SZ * SEQ)          // 8192
#define SCALE_F 0.03125f               // 1024^-0.5

// ---------------- scratch (device globals; no cudaMalloc allowed) ----------
__device__ __align__(256) float g_q[B_SZ * N_HEAD * SEQ * D_HEAD];
__device__ __align__(256) float g_k[B_SZ * N_HEAD * SEQ * D_HEAD];
__device__ __align__(256) float g_v[B_SZ * N_HEAD * SEQ * D_HEAD];
__device__ __align__(256) float g_attn[M_TOT * D_EMBED];

// ---------------------------------------------------------------------------
// helpers
// ---------------------------------------------------------------------------
__device__ __forceinline__ uint32_t smem_u32(const void* p) {
    uint32_t r;
    asm("{ .reg .u64 t; cvta.to.shared.u64 t, %1; cvt.u32.u64 %0, t; }"
        : "=r"(r) : "l"(p));
    return r;
}
__device__ __forceinline__ float f2tf32f(float f) {
    uint32_t r;
    asm("cvt.rna.tf32.f32 %0, %1;" : "=r"(r) : "f"(f));
    return __uint_as_float(r);
}

#define LDSM4(r, addr)                                                        \
    asm volatile("ldmatrix.sync.aligned.m8n8.x4.shared.b16 {%0,%1,%2,%3}, [%4];" \
                 : "=r"((r)[0]), "=r"((r)[1]), "=r"((r)[2]), "=r"((r)[3])     \
                 : "r"(addr))

#define MMA_TF32(d, a, b0, b1)                                                \
    asm volatile("mma.sync.aligned.m16n8k8.row.col.f32.tf32.tf32.f32 "        \
                 "{%0,%1,%2,%3}, {%4,%5,%6,%7}, {%8,%9}, {%0,%1,%2,%3};"      \
                 : "+f"((d)[0]), "+f"((d)[1]), "+f"((d)[2]), "+f"((d)[3])     \
                 : "r"((a)[0]), "r"((a)[1]), "r"((a)[2]), "r"((a)[3]),        \
                   "r"(b0), "r"(b1))

// ---------------------------------------------------------------------------
// tf32 mma.sync NT GEMM:  C[M,N] = A[M,K] * B[N,K]^T + bias
// CTA 128x128, BK=16, 8 warps x (64x32 tile). Double-buffered smem,
// stride-20 rows -> conflict-free LDSM. cvt.rna.tf32 at the STS stage.
// MODE 1: epilogue scatters into g_q/g_k/g_v [B,H,S,Dh].  MODE 0: -> out.
// ---------------------------------------------------------------------------
#define BM 128
#define BK 16
#define SST 20   // smem row stride (floats)

template <int MODE>
__global__ void __launch_bounds__(256)
gemm_mma(const float* __restrict__ Aparam,
         const float* __restrict__ Bw,
         const float* __restrict__ bias,
         float* __restrict__ out,
         int N, int K)
{
    const float* A = (MODE == 0) ? (const float*)g_attn : Aparam;

    __shared__ __align__(16) float As[2][BM][SST];
    __shared__ __align__(16) float Bs[2][BM][SST];

    const int tid  = threadIdx.x;
    const int wid  = tid >> 5;
    const int lane = tid & 31;
    const int m0 = blockIdx.y * BM;
    const int n0 = blockIdx.x * BM;
    const int warp_m = (wid >> 2) * 64;   // 0 or 64
    const int warp_n = (wid & 3) * 32;    // 0,32,64,96

    // global loader mapping: 2 rows per thread (lrow, lrow+64), one float4 each
    const int lrow = tid >> 2;            // 0..63
    const int lc4  = (tid & 3) * 4;       // 0,4,8,12

    const float* Ap = A  + (size_t)(m0 + lrow) * K + lc4;
    const float* Bp = Bw + (size_t)(n0 + lrow) * K + lc4;
    const size_t rstep = (size_t)64 * K;

    // ldmatrix lane addressing
    const int lrow16 = lane & 15;
    const int lkoff  = (lane >> 4) * 4;
    const uint32_t a_lm = smem_u32(&As[0][warp_m + lrow16][lkoff]);
    const uint32_t b_lm = smem_u32(&Bs[0][warp_n + lrow16][lkoff]);
    const uint32_t bufstep = (uint32_t)(BM * SST * 4);

    float c[4][4][4];
#pragma unroll
    for (int mt = 0; mt < 4; mt++)
#pragma unroll
        for (int nt = 0; nt < 4; nt++)
#pragma unroll
            for (int r = 0; r < 4; r++) c[mt][nt][r] = 0.f;

    float4 ra0, ra1, rb0, rb1;
    // prefetch chunk 0 -> buf 0
    ra0 = *(const float4*)(Ap);
    ra1 = *(const float4*)(Ap + rstep);
    rb0 = *(const float4*)(Bp);
    rb1 = *(const float4*)(Bp + rstep);
    {
        float* a0 = &As[0][lrow][lc4];
        float* a1 = &As[0][lrow + 64][lc4];
        float* b0 = &Bs[0][lrow][lc4];
        float* b1 = &Bs[0][lrow + 64][lc4];
        a0[0]=f2tf32f(ra0.x); a0[1]=f2tf32f(ra0.y); a0[2]=f2tf32f(ra0.z); a0[3]=f2tf32f(ra0.w);
        a1[0]=f2tf32f(ra1.x); a1[1]=f2tf32f(ra1.y); a1[2]=f2tf32f(ra1.z); a1[3]=f2tf32f(ra1.w);
        b0[0]=f2tf32f(rb0.x); b0[1]=f2tf32f(rb0.y); b0[2]=f2tf32f(rb0.z); b0[3]=f2tf32f(rb0.w);
        b1[0]=f2tf32f(rb1.x); b1[1]=f2tf32f(rb1.y); b1[2]=f2tf32f(rb1.z); b1[3]=f2tf32f(rb1.w);
    }
    __syncthreads();

    const int NCH = K / BK;
    for (int kb = 0; kb < NCH; kb++) {
        const int cur = kb & 1;
        if (kb + 1 < NCH) {
            const float* Ak = Ap + (kb + 1) * BK;
            const float* Bk = Bp + (kb + 1) * BK;
            ra0 = *(const float4*)(Ak);
            ra1 = *(const float4*)(Ak + rstep);
            rb0 = *(const float4*)(Bk);
            rb1 = *(const float4*)(Bk + rstep);
        }

        const uint32_t abuf = a_lm + cur * bufstep;
        const uint32_t bbuf = b_lm + cur * bufstep;
#pragma unroll
        for (int ks = 0; ks < 2; ks++) {
            uint32_t af[4][4], bf[2][4];
#pragma unroll
            for (int mt = 0; mt < 4; mt++)
                LDSM4(af[mt], abuf + (uint32_t)(mt * 16 * SST * 4 + ks * 32));
#pragma unroll
            for (int nt2 = 0; nt2 < 2; nt2++)
                LDSM4(bf[nt2], bbuf + (uint32_t)(nt2 * 16 * SST * 4 + ks * 32));
#pragma unroll
            for (int mt = 0; mt < 4; mt++)
#pragma unroll
                for (int nt = 0; nt < 4; nt++)
                    MMA_TF32(c[mt][nt], af[mt],
                             bf[nt >> 1][nt & 1], bf[nt >> 1][(nt & 1) + 2]);
        }

        if (kb + 1 < NCH) {
            const int nb = cur ^ 1;
            float* a0 = &As[nb][lrow][lc4];
            float* a1 = &As[nb][lrow + 64][lc4];
            float* b0 = &Bs[nb][lrow][lc4];
            float* b1 = &Bs[nb][lrow + 64][lc4];
            a0[0]=f2tf32f(ra0.x); a0[1]=f2tf32f(ra0.y); a0[2]=f2tf32f(ra0.z); a0[3]=f2tf32f(ra0.w);
            a1[0]=f2tf32f(ra1.x); a1[1]=f2tf32f(ra1.y); a1[2]=f2tf32f(ra1.z); a1[3]=f2tf32f(ra1.w);
            b0[0]=f2tf32f(rb0.x); b0[1]=f2tf32f(rb0.y); b0[2]=f2tf32f(rb0.z); b0[3]=f2tf32f(rb0.w);
            b1[0]=f2tf32f(rb1.x); b1[1]=f2tf32f(rb1.y); b1[2]=f2tf32f(rb1.z); b1[3]=f2tf32f(rb1.w);
        }
        __syncthreads();
    }

    // ---- epilogue ----
    const int g  = lane >> 2;          // 0..7
    const int cp = lane & 3;           // 0..3
#pragma unroll
    for (int mt = 0; mt < 4; mt++) {
        const int r0 = m0 + warp_m + mt * 16 + g;
        const int r1 = r0 + 8;
#pragma unroll
        for (int nt = 0; nt < 4; nt++) {
            const int col = n0 + warp_n + nt * 8 + cp * 2;
            const float2 b2 = *(const float2*)&bias[col];
            float2 lo, hi;
            lo.x = c[mt][nt][0] + b2.x;  lo.y = c[mt][nt][1] + b2.y;
            hi.x = c[mt][nt][2] + b2.x;  hi.y = c[mt][nt][3] + b2.y;
            if (MODE == 0) {
                *(float2*)&out[(size_t)r0 * N + col] = lo;
                *(float2*)&out[(size_t)r1 * N + col] = hi;
            } else {
                const int cc = col >> 10;            // 0=q,1=k,2=v
                const int hh = (col >> 6) & 15;
                const int dh = col & 63;
                float* dst = (cc == 0) ? g_q : (cc == 1) ? g_k : g_v;
                const int b0r = r0 >> 11, s0 = r0 & 2047;
                const int b1r = r1 >> 11, s1 = r1 & 2047;
                *(float2*)&dst[((size_t)((b0r * N_HEAD + hh) * SEQ + s0)) * D_HEAD + dh] = lo;
                *(float2*)&dst[((size_t)((b1r * N_HEAD + hh) * SEQ + s1)) * D_HEAD + dh] = hi;
            }
        }
    }
}

// ---------------------------------------------------------------------------
// Flash-attention (causal), fp32 FFMA (verified R1 version, unchanged).
// ---------------------------------------------------------------------------
#define ATT_STRIDE 68
#define ATT_SMEM_BYTES (3 * 64 * ATT_STRIDE * 4)

__global__ void __launch_bounds__(256)
attn_kernel()
{
    extern __shared__ __align__(16) float sm[];
    float* Qs  = sm;
    float* KPs = sm + 64 * ATT_STRIDE;
    float* Vs  = sm + 2 * 64 * ATT_STRIDE;

    const int qt = blockIdx.x;
    const int bh = blockIdx.y;
    const int tid = threadIdx.x;
    const int ty = tid >> 4, tx = tid & 15;

    const float* Qp = g_q + (size_t)bh * SEQ * D_HEAD;
    const float* Kp = g_k + (size_t)bh * SEQ * D_HEAD;
    const float* Vp = g_v + (size_t)bh * SEQ * D_HEAD;

    for (int idx = tid; idx < 64 * 16; idx += 256) {
        const int r  = idx >> 4;
        const int d4 = (idx & 15) * 4;
        const float4 v = *(const float4*)&Qp[(size_t)(qt * 64 + r) * D_HEAD + d4];
        Qs[(d4 + 0) * ATT_STRIDE + r] = v.x;
        Qs[(d4 + 1) * ATT_STRIDE + r] = v.y;
        Qs[(d4 + 2) * ATT_STRIDE + r] = v.z;
        Qs[(d4 + 3) * ATT_STRIDE + r] = v.w;
    }

    float o[4][4];
    float mrow[4], lrow[4];
#pragma unroll
    for (int i = 0; i < 4; i++) {
        mrow[i] = -INFINITY; lrow[i] = 0.f;
#pragma unroll
        for (int j = 0; j < 4; j++) o[i][j] = 0.f;
    }

    for (int kt = 0; kt <= qt; kt++) {
        __syncthreads();
        for (int idx = tid; idx < 64 * 16; idx += 256) {
            const int r  = idx >> 4;
            const int d4 = (idx & 15) * 4;
            const float4 kv = *(const float4*)&Kp[(size_t)(kt * 64 + r) * D_HEAD + d4];
            KPs[(d4 + 0) * ATT_STRIDE + r] = kv.x;
            KPs[(d4 + 1) * ATT_STRIDE + r] = kv.y;
            KPs[(d4 + 2) * ATT_STRIDE + r] = kv.z;
            KPs[(d4 + 3) * ATT_STRIDE + r] = kv.w;
            const float4 vv = *(const float4*)&Vp[(size_t)(kt * 64 + r) * D_HEAD + d4];
            *(float4*)&Vs[r * ATT_STRIDE + d4] = vv;
        }
        __syncthreads();

        float s[4][4];
#pragma unroll
        for (int i = 0; i < 4; i++)
#pragma unroll
            for (int j = 0; j < 4; j++) s[i][j] = 0.f;
#pragma unroll 8
        for (int d = 0; d < 64; d++) {
            const float4 a4 = *(const float4*)&Qs[d * ATT_STRIDE + ty * 4];
            const float4 b4 = *(const float4*)&KPs[d * ATT_STRIDE + tx * 4];
            const float a[4] = {a4.x, a4.y, a4.z, a4.w};
            const float b[4] = {b4.x, b4.y, b4.z, b4.w};
#pragma unroll
            for (int i = 0; i < 4; i++)
#pragma unroll
                for (int j = 0; j < 4; j++) s[i][j] += a[i] * b[j];
        }

        const int qg0 = qt * 64 + ty * 4;
        const int kg0 = kt * 64 + tx * 4;
#pragma unroll
        for (int i = 0; i < 4; i++)
#pragma unroll
            for (int j = 0; j < 4; j++) {
                s[i][j] *= SCALE_F;
                if (kt == qt && (kg0 + j) > (qg0 + i)) s[i][j] = -INFINITY;
            }

        float mt[4], mnew[4], alpha[4], rs[4];
#pragma unroll
        for (int i = 0; i < 4; i++) {
            mt[i] = fmaxf(fmaxf(s[i][0], s[i][1]), fmaxf(s[i][2], s[i][3]));
#pragma unroll
            for (int off = 8; off > 0; off >>= 1)
                mt[i] = fmaxf(mt[i], __shfl_xor_sync(0xffffffffu, mt[i], off));
            mnew[i]  = fmaxf(mrow[i], mt[i]);
            alpha[i] = expf(mrow[i] - mnew[i]);
        }
#pragma unroll
        for (int i = 0; i < 4; i++) {
            rs[i] = 0.f;
#pragma unroll
            for (int j = 0; j < 4; j++) {
                s[i][j] = expf(s[i][j] - mnew[i]);
                rs[i] += s[i][j];
            }
#pragma unroll
            for (int off = 8; off > 0; off >>= 1)
                rs[i] += __shfl_xor_sync(0xffffffffu, rs[i], off);
            lrow[i] = alpha[i] * lrow[i] + rs[i];
            mrow[i] = mnew[i];
#pragma unroll
            for (int j = 0; j < 4; j++) o[i][j] *= alpha[i];
        }

        __syncthreads();
#pragma unroll
        for (int j = 0; j < 4; j++) {
            float4 pv;
            pv.x = s[0][j]; pv.y = s[1][j]; pv.z = s[2][j]; pv.w = s[3][j];
            *(float4*)&KPs[(tx * 4 + j) * ATT_STRIDE + ty * 4] = pv;
        }
        __syncthreads();

#pragma unroll 8
        for (int k = 0; k < 64; k++) {
            const float4 a4 = *(const float4*)&KPs[k * ATT_STRIDE + ty * 4];
            const float4 b4 = *(const float4*)&Vs[k * ATT_STRIDE + tx * 4];
            const float a[4] = {a4.x, a4.y, a4.z, a4.w};
            const float b[4] = {b4.x, b4.y, b4.z, b4.w};
#pragma unroll
            for (int i = 0; i < 4; i++)
#pragma unroll
                for (int j = 0; j < 4; j++) o[i][j] += a[i] * b[j];
        }
    }

    const int b = bh >> 4, h = bh & 15;
#pragma unroll
    for (int i = 0; i < 4; i++) {
        const float inv = 1.f / lrow[i];
        const int sg = qt * 64 + ty * 4 + i;
        float4 r;
        r.x = o[i][0] * inv; r.y = o[i][1] * inv;
        r.z = o[i][2] * inv; r.w = o[i][3] * inv;
        *(float4*)&g_attn[((size_t)(b * SEQ + sg)) * D_EMBED + h * D_HEAD + tx * 4] = r;
    }
}

// ---------------------------------------------------------------------------
extern "C" void kernel_launch(void* const* d_in, const int* in_sizes, int n_in,
                              void* d_out, int out_size)
{
    const float* x     = (const float*)d_in[0];
    const float* w_in  = (const float*)d_in[1];
    const float* b_in  = (const float*)d_in[2];
    const float* w_out = (const float*)d_in[3];
    const float* b_out = (const float*)d_in[4];
    float* out = (float*)d_out;
    (void)in_sizes; (void)n_in; (void)out_size;

    cudaFuncSetAttribute(attn_kernel,
                         cudaFuncAttributeMaxDynamicSharedMemorySize,
                         ATT_SMEM_BYTES);

    // 1) QKV projection + bias -> g_q/g_k/g_v  (tf32 mma.sync)
    gemm_mma<1><<<dim3(3 * D_EMBED / 128, M_TOT / 128), 256>>>(
        x, w_in, b_in, nullptr, 3 * D_EMBED, D_EMBED);

    // 2) causal flash attention -> g_attn [B,S,D]
    attn_kernel<<<dim3(SEQ / 64, B_SZ * N_HEAD), 256, ATT_SMEM_BYTES>>>();

    // 3) output projection + bias (tf32 mma.sync)
    gemm_mma<0><<<dim3(D_EMBED / 128, M_TOT / 128), 256>>>(
        nullptr, w_out, b_out, out, D_EMBED, D_EMBED);
}

// round 4
// speedup vs baseline: 1.7703x; 1.0101x over previous
#include <cuda_runtime.h>
#include <math.h>
#include <stdint.h>

#define D_EMBED 1024
#define N_HEAD  16
#define D_HEAD  64
#define B_SZ    4
#define SEQ     2048
#define M_TOT   (B_SZ * SEQ)          // 8192
#define SCALE_F 0.03125f               // 1024^-0.5

// ---------------- scratch (device globals; no cudaMalloc allowed) ----------
__device__ __align__(256) float g_q[B_SZ * N_HEAD * SEQ * D_HEAD];
__device__ __align__(256) float g_k[B_SZ * N_HEAD * SEQ * D_HEAD];
__device__ __align__(256) float g_v[B_SZ * N_HEAD * SEQ * D_HEAD];
__device__ __align__(256) float g_attn[M_TOT * D_EMBED];

// ---------------------------------------------------------------------------
// helpers
// ---------------------------------------------------------------------------
__device__ __forceinline__ uint32_t smem_u32(const void* p) {
    uint32_t r;
    asm("{ .reg .u64 t; cvta.to.shared.u64 t, %1; cvt.u32.u64 %0, t; }"
        : "=r"(r) : "l"(p));
    return r;
}
__device__ __forceinline__ float f2tf32f(float f) {
    uint32_t r;
    asm("cvt.rna.tf32.f32 %0, %1;" : "=r"(r) : "f"(f));
    return __uint_as_float(r);
}

#define LDSM4(r, addr)                                                        \
    asm volatile("ldmatrix.sync.aligned.m8n8.x4.shared.b16 {%0,%1,%2,%3}, [%4];" \
                 : "=r"((r)[0]), "=r"((r)[1]), "=r"((r)[2]), "=r"((r)[3])     \
                 : "r"(addr))

#define MMA_TF32(d, a, b0, b1)                                                \
    asm volatile("mma.sync.aligned.m16n8k8.row.col.f32.tf32.tf32.f32 "        \
                 "{%0,%1,%2,%3}, {%4,%5,%6,%7}, {%8,%9}, {%0,%1,%2,%3};"      \
                 : "+f"((d)[0]), "+f"((d)[1]), "+f"((d)[2]), "+f"((d)[3])     \
                 : "r"((a)[0]), "r"((a)[1]), "r"((a)[2]), "r"((a)[3]),        \
                   "r"(b0), "r"(b1))

// ---------------------------------------------------------------------------
// tf32 mma.sync NT GEMM:  C[M,N] = A[M,K] * B[N,K]^T + bias
// CTA 128x128, BK=16, 8 warps x (64x32 tile). Double-buffered smem,
// stride-20 rows -> conflict-free LDSM. cvt.rna.tf32 at the STS stage.
// MODE 1: epilogue scatters into g_q/g_k/g_v [B,H,S,Dh].  MODE 0: -> out.
// ---------------------------------------------------------------------------
#define BM 128
#define BK 16
#define SST 20   // smem row stride (floats)

template <int MODE>
__global__ void __launch_bounds__(256)
gemm_mma(const float* __restrict__ Aparam,
         const float* __restrict__ Bw,
         const float* __restrict__ bias,
         float* __restrict__ out,
         int N, int K)
{
    const float* A = (MODE == 0) ? (const float*)g_attn : Aparam;

    __shared__ __align__(16) float As[2][BM][SST];
    __shared__ __align__(16) float Bs[2][BM][SST];

    const int tid  = threadIdx.x;
    const int wid  = tid >> 5;
    const int lane = tid & 31;
    const int m0 = blockIdx.y * BM;
    const int n0 = blockIdx.x * BM;
    const int warp_m = (wid >> 2) * 64;   // 0 or 64
    const int warp_n = (wid & 3) * 32;    // 0,32,64,96

    // global loader mapping: 2 rows per thread (lrow, lrow+64), one float4 each
    const int lrow = tid >> 2;            // 0..63
    const int lc4  = (tid & 3) * 4;       // 0,4,8,12

    const float* Ap = A  + (size_t)(m0 + lrow) * K + lc4;
    const float* Bp = Bw + (size_t)(n0 + lrow) * K + lc4;
    const size_t rstep = (size_t)64 * K;

    // ldmatrix lane addressing
    const int lrow16 = lane & 15;
    const int lkoff  = (lane >> 4) * 4;
    const uint32_t a_lm = smem_u32(&As[0][warp_m + lrow16][lkoff]);
    const uint32_t b_lm = smem_u32(&Bs[0][warp_n + lrow16][lkoff]);
    const uint32_t bufstep = (uint32_t)(BM * SST * 4);

    float c[4][4][4];
#pragma unroll
    for (int mt = 0; mt < 4; mt++)
#pragma unroll
        for (int nt = 0; nt < 4; nt++)
#pragma unroll
            for (int r = 0; r < 4; r++) c[mt][nt][r] = 0.f;

    float4 ra0, ra1, rb0, rb1;
    // prefetch chunk 0 -> buf 0
    ra0 = *(const float4*)(Ap);
    ra1 = *(const float4*)(Ap + rstep);
    rb0 = *(const float4*)(Bp);
    rb1 = *(const float4*)(Bp + rstep);
    {
        float* a0 = &As[0][lrow][lc4];
        float* a1 = &As[0][lrow + 64][lc4];
        float* b0 = &Bs[0][lrow][lc4];
        float* b1 = &Bs[0][lrow + 64][lc4];
        a0[0]=f2tf32f(ra0.x); a0[1]=f2tf32f(ra0.y); a0[2]=f2tf32f(ra0.z); a0[3]=f2tf32f(ra0.w);
        a1[0]=f2tf32f(ra1.x); a1[1]=f2tf32f(ra1.y); a1[2]=f2tf32f(ra1.z); a1[3]=f2tf32f(ra1.w);
        b0[0]=f2tf32f(rb0.x); b0[1]=f2tf32f(rb0.y); b0[2]=f2tf32f(rb0.z); b0[3]=f2tf32f(rb0.w);
        b1[0]=f2tf32f(rb1.x); b1[1]=f2tf32f(rb1.y); b1[2]=f2tf32f(rb1.z); b1[3]=f2tf32f(rb1.w);
    }
    __syncthreads();

    const int NCH = K / BK;
    for (int kb = 0; kb < NCH; kb++) {
        const int cur = kb & 1;
        if (kb + 1 < NCH) {
            const float* Ak = Ap + (kb + 1) * BK;
            const float* Bk = Bp + (kb + 1) * BK;
            ra0 = *(const float4*)(Ak);
            ra1 = *(const float4*)(Ak + rstep);
            rb0 = *(const float4*)(Bk);
            rb1 = *(const float4*)(Bk + rstep);
        }

        const uint32_t abuf = a_lm + cur * bufstep;
        const uint32_t bbuf = b_lm + cur * bufstep;
#pragma unroll
        for (int ks = 0; ks < 2; ks++) {
            uint32_t af[4][4], bf[2][4];
#pragma unroll
            for (int mt = 0; mt < 4; mt++)
                LDSM4(af[mt], abuf + (uint32_t)(mt * 16 * SST * 4 + ks * 32));
#pragma unroll
            for (int nt2 = 0; nt2 < 2; nt2++)
                LDSM4(bf[nt2], bbuf + (uint32_t)(nt2 * 16 * SST * 4 + ks * 32));
#pragma unroll
            for (int mt = 0; mt < 4; mt++)
#pragma unroll
                for (int nt = 0; nt < 4; nt++)
                    MMA_TF32(c[mt][nt], af[mt],
                             bf[nt >> 1][nt & 1], bf[nt >> 1][(nt & 1) + 2]);
        }

        if (kb + 1 < NCH) {
            const int nb = cur ^ 1;
            float* a0 = &As[nb][lrow][lc4];
            float* a1 = &As[nb][lrow + 64][lc4];
            float* b0 = &Bs[nb][lrow][lc4];
            float* b1 = &Bs[nb][lrow + 64][lc4];
            a0[0]=f2tf32f(ra0.x); a0[1]=f2tf32f(ra0.y); a0[2]=f2tf32f(ra0.z); a0[3]=f2tf32f(ra0.w);
            a1[0]=f2tf32f(ra1.x); a1[1]=f2tf32f(ra1.y); a1[2]=f2tf32f(ra1.z); a1[3]=f2tf32f(ra1.w);
            b0[0]=f2tf32f(rb0.x); b0[1]=f2tf32f(rb0.y); b0[2]=f2tf32f(rb0.z); b0[3]=f2tf32f(rb0.w);
            b1[0]=f2tf32f(rb1.x); b1[1]=f2tf32f(rb1.y); b1[2]=f2tf32f(rb1.z); b1[3]=f2tf32f(rb1.w);
        }
        __syncthreads();
    }

    // ---- epilogue ----
    const int g  = lane >> 2;          // 0..7
    const int cp = lane & 3;           // 0..3
#pragma unroll
    for (int mt = 0; mt < 4; mt++) {
        const int r0 = m0 + warp_m + mt * 16 + g;
        const int r1 = r0 + 8;
#pragma unroll
        for (int nt = 0; nt < 4; nt++) {
            const int col = n0 + warp_n + nt * 8 + cp * 2;
            const float2 b2 = *(const float2*)&bias[col];
            float2 lo, hi;
            lo.x = c[mt][nt][0] + b2.x;  lo.y = c[mt][nt][1] + b2.y;
            hi.x = c[mt][nt][2] + b2.x;  hi.y = c[mt][nt][3] + b2.y;
            if (MODE == 0) {
                *(float2*)&out[(size_t)r0 * N + col] = lo;
                *(float2*)&out[(size_t)r1 * N + col] = hi;
            } else {
                const int cc = col >> 10;            // 0=q,1=k,2=v
                const int hh = (col >> 6) & 15;
                const int dh = col & 63;
                float* dst = (cc == 0) ? g_q : (cc == 1) ? g_k : g_v;
                const int b0r = r0 >> 11, s0 = r0 & 2047;
                const int b1r = r1 >> 11, s1 = r1 & 2047;
                *(float2*)&dst[((size_t)((b0r * N_HEAD + hh) * SEQ + s0)) * D_HEAD + dh] = lo;
                *(float2*)&dst[((size_t)((b1r * N_HEAD + hh) * SEQ + s1)) * D_HEAD + dh] = hi;
            }
        }
    }
}

// ---------------------------------------------------------------------------
// Flash-attention (causal), fp32 FFMA (verified R1 version, unchanged).
// ---------------------------------------------------------------------------
#define ATT_STRIDE 68
#define ATT_SMEM_BYTES (3 * 64 * ATT_STRIDE * 4)

__global__ void __launch_bounds__(256)
attn_kernel()
{
    extern __shared__ __align__(16) float sm[];
    float* Qs  = sm;
    float* KPs = sm + 64 * ATT_STRIDE;
    float* Vs  = sm + 2 * 64 * ATT_STRIDE;

    const int qt = blockIdx.x;
    const int bh = blockIdx.y;
    const int tid = threadIdx.x;
    const int ty = tid >> 4, tx = tid & 15;

    const float* Qp = g_q + (size_t)bh * SEQ * D_HEAD;
    const float* Kp = g_k + (size_t)bh * SEQ * D_HEAD;
    const float* Vp = g_v + (size_t)bh * SEQ * D_HEAD;

    for (int idx = tid; idx < 64 * 16; idx += 256) {
        const int r  = idx >> 4;
        const int d4 = (idx & 15) * 4;
        const float4 v = *(const float4*)&Qp[(size_t)(qt * 64 + r) * D_HEAD + d4];
        Qs[(d4 + 0) * ATT_STRIDE + r] = v.x;
        Qs[(d4 + 1) * ATT_STRIDE + r] = v.y;
        Qs[(d4 + 2) * ATT_STRIDE + r] = v.z;
        Qs[(d4 + 3) * ATT_STRIDE + r] = v.w;
    }

    float o[4][4];
    float mrow[4], lrow[4];
#pragma unroll
    for (int i = 0; i < 4; i++) {
        mrow[i] = -INFINITY; lrow[i] = 0.f;
#pragma unroll
        for (int j = 0; j < 4; j++) o[i][j] = 0.f;
    }

    for (int kt = 0; kt <= qt; kt++) {
        __syncthreads();
        for (int idx = tid; idx < 64 * 16; idx += 256) {
            const int r  = idx >> 4;
            const int d4 = (idx & 15) * 4;
            const float4 kv = *(const float4*)&Kp[(size_t)(kt * 64 + r) * D_HEAD + d4];
            KPs[(d4 + 0) * ATT_STRIDE + r] = kv.x;
            KPs[(d4 + 1) * ATT_STRIDE + r] = kv.y;
            KPs[(d4 + 2) * ATT_STRIDE + r] = kv.z;
            KPs[(d4 + 3) * ATT_STRIDE + r] = kv.w;
            const float4 vv = *(const float4*)&Vp[(size_t)(kt * 64 + r) * D_HEAD + d4];
            *(float4*)&Vs[r * ATT_STRIDE + d4] = vv;
        }
        __syncthreads();

        float s[4][4];
#pragma unroll
        for (int i = 0; i < 4; i++)
#pragma unroll
            for (int j = 0; j < 4; j++) s[i][j] = 0.f;
#pragma unroll 8
        for (int d = 0; d < 64; d++) {
            const float4 a4 = *(const float4*)&Qs[d * ATT_STRIDE + ty * 4];
            const float4 b4 = *(const float4*)&KPs[d * ATT_STRIDE + tx * 4];
            const float a[4] = {a4.x, a4.y, a4.z, a4.w};
            const float b[4] = {b4.x, b4.y, b4.z, b4.w};
#pragma unroll
            for (int i = 0; i < 4; i++)
#pragma unroll
                for (int j = 0; j < 4; j++) s[i][j] += a[i] * b[j];
        }

        const int qg0 = qt * 64 + ty * 4;
        const int kg0 = kt * 64 + tx * 4;
#pragma unroll
        for (int i = 0; i < 4; i++)
#pragma unroll
            for (int j = 0; j < 4; j++) {
                s[i][j] *= SCALE_F;
                if (kt == qt && (kg0 + j) > (qg0 + i)) s[i][j] = -INFINITY;
            }

        float mt[4], mnew[4], alpha[4], rs[4];
#pragma unroll
        for (int i = 0; i < 4; i++) {
            mt[i] = fmaxf(fmaxf(s[i][0], s[i][1]), fmaxf(s[i][2], s[i][3]));
#pragma unroll
            for (int off = 8; off > 0; off >>= 1)
                mt[i] = fmaxf(mt[i], __shfl_xor_sync(0xffffffffu, mt[i], off));
            mnew[i]  = fmaxf(mrow[i], mt[i]);
            alpha[i] = expf(mrow[i] - mnew[i]);
        }
#pragma unroll
        for (int i = 0; i < 4; i++) {
            rs[i] = 0.f;
#pragma unroll
            for (int j = 0; j < 4; j++) {
                s[i][j] = expf(s[i][j] - mnew[i]);
                rs[i] += s[i][j];
            }
#pragma unroll
            for (int off = 8; off > 0; off >>= 1)
                rs[i] += __shfl_xor_sync(0xffffffffu, rs[i], off);
            lrow[i] = alpha[i] * lrow[i] + rs[i];
            mrow[i] = mnew[i];
#pragma unroll
            for (int j = 0; j < 4; j++) o[i][j] *= alpha[i];
        }

        __syncthreads();
#pragma unroll
        for (int j = 0; j < 4; j++) {
            float4 pv;
            pv.x = s[0][j]; pv.y = s[1][j]; pv.z = s[2][j]; pv.w = s[3][j];
            *(float4*)&KPs[(tx * 4 + j) * ATT_STRIDE + ty * 4] = pv;
        }
        __syncthreads();

#pragma unroll 8
        for (int k = 0; k < 64; k++) {
            const float4 a4 = *(const float4*)&KPs[k * ATT_STRIDE + ty * 4];
            const float4 b4 = *(const float4*)&Vs[k * ATT_STRIDE + tx * 4];
            const float a[4] = {a4.x, a4.y, a4.z, a4.w};
            const float b[4] = {b4.x, b4.y, b4.z, b4.w};
#pragma unroll
            for (int i = 0; i < 4; i++)
#pragma unroll
                for (int j = 0; j < 4; j++) o[i][j] += a[i] * b[j];
        }
    }

    const int b = bh >> 4, h = bh & 15;
#pragma unroll
    for (int i = 0; i < 4; i++) {
        const float inv = 1.f / lrow[i];
        const int sg = qt * 64 + ty * 4 + i;
        float4 r;
        r.x = o[i][0] * inv; r.y = o[i][1] * inv;
        r.z = o[i][2] * inv; r.w = o[i][3] * inv;
        *(float4*)&g_attn[((size_t)(b * SEQ + sg)) * D_EMBED + h * D_HEAD + tx * 4] = r;
    }
}

// ---------------------------------------------------------------------------
extern "C" void kernel_launch(void* const* d_in, const int* in_sizes, int n_in,
                              void* d_out, int out_size)
{
    const float* x     = (const float*)d_in[0];
    const float* w_in  = (const float*)d_in[1];
    const float* b_in  = (const float*)d_in[2];
    const float* w_out = (const float*)d_in[3];
    const float* b_out = (const float*)d_in[4];
    float* out = (float*)d_out;
    (void)in_sizes; (void)n_in; (void)out_size;

    cudaFuncSetAttribute(attn_kernel,
                         cudaFuncAttributeMaxDynamicSharedMemorySize,
                         ATT_SMEM_BYTES);

    // 1) QKV projection + bias -> g_q/g_k/g_v  (tf32 mma.sync)
    gemm_mma<1><<<dim3(3 * D_EMBED / 128, M_TOT / 128), 256>>>(
        x, w_in, b_in, nullptr, 3 * D_EMBED, D_EMBED);

    // 2) causal flash attention -> g_attn [B,S,D]
    attn_kernel<<<dim3(SEQ / 64, B_SZ * N_HEAD), 256, ATT_SMEM_BYTES>>>();

    // 3) output projection + bias (tf32 mma.sync)
    gemm_mma<0><<<dim3(D_EMBED / 128, M_TOT / 128), 256>>>(
        nullptr, w_out, b_out, out, D_EMBED, D_EMBED);
}